// round 1
// baseline (speedup 1.0000x reference)
#include <cuda_runtime.h>

// Problem constants (fixed by the episode configuration)
#define BB     8            // episodes
#define NWAY   10           // N ways
#define KSHOT  5            // K shots (adapt)
#define QN     500          // queries per episode
#define DD     768          // hidden dim
#define NQ     (BB * QN)    // 4000 total queries
#define NL     (NWAY + 1)   // 11 logits after min-append

// Prototype scratch: S[b, n, d] = mean_k support[((b*N+n)*K+k), d]
__device__ float g_S[BB * NWAY * DD];

// ---------------------------------------------------------------------------
// Kernel 1: prototypes. One thread per output element, coalesced over d.
// ---------------------------------------------------------------------------
__global__ void __launch_bounds__(256) proto_kernel(const float* __restrict__ sup) {
    int idx = blockIdx.x * blockDim.x + threadIdx.x;   // over B*N*D = 61440
    if (idx >= BB * NWAY * DD) return;
    int d  = idx % DD;
    int bn = idx / DD;                                  // b*NWAY + n
    const float* base = sup + (size_t)(bn * KSHOT) * DD + d;
    float s = 0.0f;
#pragma unroll
    for (int k = 0; k < KSHOT; k++) s += base[(size_t)k * DD];
    g_S[idx] = s * 0.2f;
}

// ---------------------------------------------------------------------------
// Kernel 2: one warp per query.
//   logits[n] = -sum_d (S[b,n,d] - q[d])^2
// then min-append, softmax, argmax, and the four outputs.
// ---------------------------------------------------------------------------
__global__ void __launch_bounds__(256) main_kernel(const float* __restrict__ qin,
                                                   float* __restrict__ out,
                                                   int out_size) {
    int gtid = blockIdx.x * blockDim.x + threadIdx.x;
    int wid  = gtid >> 5;               // query index
    int lane = threadIdx.x & 31;
    if (wid >= NQ) return;

    int b = wid / QN;

    const float4* __restrict__ qv = (const float4*)(qin + (size_t)wid * DD);
    const float4* __restrict__ sv = (const float4*)(g_S + (size_t)b * NWAY * DD);

    // Load this query's 768 floats: 6 float4 per lane, coalesced (lane + 32*j)
    float4 qr[6];
#pragma unroll
    for (int j = 0; j < 6; j++) qr[j] = qv[lane + 32 * j];

    float acc[NWAY];
#pragma unroll
    for (int n = 0; n < NWAY; n++) acc[n] = 0.0f;

#pragma unroll
    for (int n = 0; n < NWAY; n++) {
#pragma unroll
        for (int j = 0; j < 6; j++) {
            float4 s = sv[n * (DD / 4) + lane + 32 * j];
            float dx = s.x - qr[j].x;
            float dy = s.y - qr[j].y;
            float dz = s.z - qr[j].z;
            float dw = s.w - qr[j].w;
            acc[n] -= dx * dx + dy * dy + dz * dz + dw * dw;
        }
    }

    // Warp butterfly reduction of all 10 accumulators
#pragma unroll
    for (int n = 0; n < NWAY; n++) {
#pragma unroll
        for (int off = 16; off; off >>= 1)
            acc[n] += __shfl_xor_sync(0xffffffffu, acc[n], off);
    }

    if (lane == 0) {
        float lg[NL];
        float mn = acc[0], mx = acc[0];
#pragma unroll
        for (int n = 0; n < NWAY; n++) {
            lg[n] = acc[n];
            mn = fminf(mn, acc[n]);
            mx = fmaxf(mx, acc[n]);
        }
        lg[NWAY] = mn - 1.0f;   // appended column: min - 1 (never the max)

        float ex[NL];
        float se = 0.0f;
#pragma unroll
        for (int i = 0; i < NL; i++) {
            ex[i] = __expf(lg[i] - mx);
            se += ex[i];
        }
        float inv = 1.0f / se;

        // argmax with first-occurrence semantics (strict >)
        int   amax = 0;
        float bv   = lg[0];
#pragma unroll
        for (int i = 1; i < NL; i++) {
            if (lg[i] > bv) { bv = lg[i]; amax = i; }
        }

        // Output layout (float32, concatenated tuple):
        //   fh     [NQ*NL]  @ 0
        //   ph     [NQ*NL]  @ NQ*NL
        //   yh_top [NQ]     @ 2*NQ*NL
        //   ph_top [NQ]     @ 2*NQ*NL + NQ
        float* fh = out + (size_t)wid * NL;
#pragma unroll
        for (int i = 0; i < NL; i++) fh[i] = lg[i];

        if (out_size >= 2 * NQ * NL) {
            float* ph = out + (size_t)NQ * NL + (size_t)wid * NL;
#pragma unroll
            for (int i = 0; i < NL; i++) ph[i] = ex[i] * inv;
        }
        if (out_size >= 2 * NQ * NL + NQ)
            out[2 * NQ * NL + wid] = (float)amax;
        if (out_size >= 2 * NQ * NL + 2 * NQ)
            out[2 * NQ * NL + NQ + wid] = ex[amax] * inv;   // ph_top = max softmax
    }
}

extern "C" void kernel_launch(void* const* d_in, const int* in_sizes, int n_in,
                              void* d_out, int out_size) {
    const float* support = (const float*)d_in[0];
    const float* query   = (const float*)d_in[1];
    float* out = (float*)d_out;

    // Kernel 1: prototypes (B*N*D = 61440 elements)
    proto_kernel<<<(BB * NWAY * DD + 255) / 256, 256>>>(support);

    // Kernel 2: one warp per query -> NQ*32 threads
    main_kernel<<<(NQ * 32 + 255) / 256, 256>>>(query, out, out_size);
}

// round 2
// speedup vs baseline: 1.1253x; 1.1253x over previous
#include <cuda_runtime.h>

#define BB     8
#define NWAY   10
#define KSHOT  5
#define QN     500
#define DD     768
#define NQ     (BB * QN)        // 4000
#define NL     (NWAY + 1)       // 11
#define QPW    4                // queries per warp
#define WTOT   (NQ / QPW)       // 1000 warps
#define WPE    (QN / QPW)       // 125 warps per episode (exact)

// Prototypes S[b,n,d] and their squared norms ssq[b,n]
__device__ float g_S[BB * NWAY * DD];
__device__ float g_ssq[BB * NWAY];

// ---------------------------------------------------------------------------
// Kernel 1: prototypes + squared norms. One block per (b,n).
// ---------------------------------------------------------------------------
__global__ void __launch_bounds__(128) proto_kernel(const float* __restrict__ sup) {
    int bn = blockIdx.x;            // 0..79
    int t  = threadIdx.x;           // 0..127
    const float* base = sup + (size_t)bn * KSHOT * DD;
    float part = 0.0f;
#pragma unroll
    for (int j = 0; j < DD / 128; j++) {
        int d = t + j * 128;
        float s = 0.0f;
#pragma unroll
        for (int k = 0; k < KSHOT; k++) s += base[k * DD + d];
        s *= 0.2f;
        g_S[bn * DD + d] = s;
        part += s * s;
    }
#pragma unroll
    for (int off = 16; off; off >>= 1)
        part += __shfl_xor_sync(0xffffffffu, part, off);
    __shared__ float red[4];
    if ((t & 31) == 0) red[t >> 5] = part;
    __syncthreads();
    if (t == 0) g_ssq[bn] = red[0] + red[1] + red[2] + red[3];
}

// ---------------------------------------------------------------------------
// Kernel 2: one warp per 4 queries.  logits[n] = 2 s·q - ||s||^2 - ||q||^2
// ---------------------------------------------------------------------------
__global__ void __launch_bounds__(256, 1) main_kernel(const float* __restrict__ qin,
                                                      float* __restrict__ out,
                                                      int out_size) {
    int wid  = blockIdx.x * 8 + (threadIdx.x >> 5);   // 0..999
    int lane = threadIdx.x & 31;
    if (wid >= WTOT) return;

    int b     = wid / WPE;
    int qbase = b * QN + (wid % WPE) * QPW;

    // Preload ssq for this episode into lane registers (latency hidden by mainloop)
    float ssq_r = (lane < NWAY) ? g_ssq[b * NWAY + lane] : 0.0f;

    const float4* __restrict__ qv = (const float4*)(qin + (size_t)qbase * DD);
    const float4* __restrict__ sv = (const float4*)(g_S + (size_t)b * NWAY * DD);

    float dot[QPW][NWAY];
    float qsq[QPW];
#pragma unroll
    for (int qi = 0; qi < QPW; qi++) {
        qsq[qi] = 0.0f;
#pragma unroll
        for (int n = 0; n < NWAY; n++) dot[qi][n] = 0.0f;
    }

#pragma unroll
    for (int j = 0; j < 6; j++) {
        float4 q[QPW];
#pragma unroll
        for (int qi = 0; qi < QPW; qi++)
            q[qi] = qv[qi * (DD / 4) + lane + 32 * j];
#pragma unroll
        for (int qi = 0; qi < QPW; qi++)
            qsq[qi] += q[qi].x * q[qi].x + q[qi].y * q[qi].y
                     + q[qi].z * q[qi].z + q[qi].w * q[qi].w;
#pragma unroll
        for (int n = 0; n < NWAY; n++) {
            float4 s = sv[n * (DD / 4) + lane + 32 * j];
#pragma unroll
            for (int qi = 0; qi < QPW; qi++) {
                dot[qi][n] += s.x * q[qi].x + s.y * q[qi].y
                            + s.z * q[qi].z + s.w * q[qi].w;
            }
        }
    }

    // Butterfly-reduce the 44 accumulators across the warp
#pragma unroll
    for (int qi = 0; qi < QPW; qi++) {
#pragma unroll
        for (int n = 0; n < NWAY; n++) {
#pragma unroll
            for (int off = 16; off; off >>= 1)
                dot[qi][n] += __shfl_xor_sync(0xffffffffu, dot[qi][n], off);
        }
#pragma unroll
        for (int off = 16; off; off >>= 1)
            qsq[qi] += __shfl_xor_sync(0xffffffffu, qsq[qi], off);
    }

    // Epilogue: all lanes compute (converged shuffles); lanes 0..3 store.
    int   qi = lane & 3;
    int   q  = qbase + qi;
    float myqsq = qsq[qi];

    float lg[NL];
    float mn =  3.4e38f, mx = -3.4e38f;
#pragma unroll
    for (int n = 0; n < NWAY; n++) {
        float sn = __shfl_sync(0xffffffffu, ssq_r, n);
        float v  = 2.0f * dot[qi][n] - sn - myqsq;
        lg[n] = v;
        mn = fminf(mn, v);
        mx = fmaxf(mx, v);
    }
    lg[NWAY] = mn - 1.0f;

    float ex[NL];
    float se = 0.0f;
#pragma unroll
    for (int i = 0; i < NL; i++) {
        ex[i] = __expf(lg[i] - mx);
        se += ex[i];
    }
    float inv = 1.0f / se;

    int   amax = 0;
    float bv   = lg[0];
#pragma unroll
    for (int i = 1; i < NL; i++)
        if (lg[i] > bv) { bv = lg[i]; amax = i; }

    if (lane < QPW) {
        // Output layout: fh[NQ*NL] | ph[NQ*NL] | yh_top[NQ] | ph_top[NQ]
        float* fh = out + (size_t)q * NL;
#pragma unroll
        for (int i = 0; i < NL; i++) fh[i] = lg[i];

        if (out_size >= 2 * NQ * NL) {
            float* ph = out + (size_t)NQ * NL + (size_t)q * NL;
#pragma unroll
            for (int i = 0; i < NL; i++) ph[i] = ex[i] * inv;
        }
        if (out_size >= 2 * NQ * NL + NQ)
            out[2 * NQ * NL + q] = (float)amax;
        if (out_size >= 2 * NQ * NL + 2 * NQ)
            out[2 * NQ * NL + NQ + q] = ex[amax] * inv;
    }
}

extern "C" void kernel_launch(void* const* d_in, const int* in_sizes, int n_in,
                              void* d_out, int out_size) {
    const float* support = (const float*)d_in[0];
    const float* query   = (const float*)d_in[1];
    float* out = (float*)d_out;

    proto_kernel<<<BB * NWAY, 128>>>(support);
    main_kernel<<<WTOT / 8, 256>>>(query, out, out_size);
}

// round 3
// speedup vs baseline: 1.1513x; 1.0231x over previous
#include <cuda_runtime.h>

#define BB     8
#define NWAY   10
#define KSHOT  5
#define QN     500
#define DD     768
#define NQ     (BB * QN)        // 4000
#define NL     (NWAY + 1)       // 11
#define QPW    2                // queries per warp
#define WTOT   (NQ / QPW)       // 2000 warps
#define WPE    (QN / QPW)       // 250 warps per episode (exact)
#define BLKW   4                // warps per block
#define NBLK   (WTOT / BLKW)    // 500 blocks

// Prototypes S[b,n,d] and their squared norms ssq[b,n]
__device__ float g_S[BB * NWAY * DD];
__device__ float g_ssq[BB * NWAY];

// ---------------------------------------------------------------------------
// Kernel 1: prototypes + squared norms. One block per (b,n).
// ---------------------------------------------------------------------------
__global__ void __launch_bounds__(128) proto_kernel(const float* __restrict__ sup) {
    int bn = blockIdx.x;            // 0..79
    int t  = threadIdx.x;           // 0..127
    const float* base = sup + (size_t)bn * KSHOT * DD;
    float part = 0.0f;
#pragma unroll
    for (int j = 0; j < DD / 128; j++) {
        int d = t + j * 128;
        float s = 0.0f;
#pragma unroll
        for (int k = 0; k < KSHOT; k++) s += base[k * DD + d];
        s *= 0.2f;
        g_S[bn * DD + d] = s;
        part += s * s;
    }
#pragma unroll
    for (int off = 16; off; off >>= 1)
        part += __shfl_xor_sync(0xffffffffu, part, off);
    __shared__ float red[4];
    if ((t & 31) == 0) red[t >> 5] = part;
    __syncthreads();
    if (t == 0) g_ssq[bn] = red[0] + red[1] + red[2] + red[3];
}

// ---------------------------------------------------------------------------
// Kernel 2: one warp per 2 queries.  logits[n] = 2 s·q - ||s||^2 - ||q||^2
// 2000 warps / 500 blocks of 128 threads; reg-capped for >=6 blocks/SM.
// ---------------------------------------------------------------------------
__global__ void __launch_bounds__(128, 6) main_kernel(const float* __restrict__ qin,
                                                      float* __restrict__ out,
                                                      int out_size) {
    int wid  = blockIdx.x * BLKW + (threadIdx.x >> 5);   // 0..1999
    int lane = threadIdx.x & 31;

    int b     = wid / WPE;
    int qbase = b * QN + (wid % WPE) * QPW;

    // Preload ssq for this episode (latency hidden behind mainloop)
    float ssq_r = (lane < NWAY) ? g_ssq[b * NWAY + lane] : 0.0f;

    const float4* __restrict__ qv = (const float4*)(qin + (size_t)qbase * DD);
    const float4* __restrict__ sv = (const float4*)(g_S + (size_t)b * NWAY * DD);

    float dot[QPW][NWAY];
    float qsq[QPW];
#pragma unroll
    for (int qi = 0; qi < QPW; qi++) {
        qsq[qi] = 0.0f;
#pragma unroll
        for (int n = 0; n < NWAY; n++) dot[qi][n] = 0.0f;
    }

#pragma unroll
    for (int j = 0; j < 6; j++) {
        float4 q[QPW];
#pragma unroll
        for (int qi = 0; qi < QPW; qi++)
            q[qi] = qv[qi * (DD / 4) + lane + 32 * j];
#pragma unroll
        for (int qi = 0; qi < QPW; qi++)
            qsq[qi] += q[qi].x * q[qi].x + q[qi].y * q[qi].y
                     + q[qi].z * q[qi].z + q[qi].w * q[qi].w;
#pragma unroll
        for (int n = 0; n < NWAY; n++) {
            float4 s = sv[n * (DD / 4) + lane + 32 * j];
#pragma unroll
            for (int qi = 0; qi < QPW; qi++) {
                dot[qi][n] += s.x * q[qi].x + s.y * q[qi].y
                            + s.z * q[qi].z + s.w * q[qi].w;
            }
        }
    }

    // Butterfly-reduce 22 accumulators across the warp
#pragma unroll
    for (int qi = 0; qi < QPW; qi++) {
#pragma unroll
        for (int n = 0; n < NWAY; n++) {
#pragma unroll
            for (int off = 16; off; off >>= 1)
                dot[qi][n] += __shfl_xor_sync(0xffffffffu, dot[qi][n], off);
        }
#pragma unroll
        for (int off = 16; off; off >>= 1)
            qsq[qi] += __shfl_xor_sync(0xffffffffu, qsq[qi], off);
    }

    // Epilogue: all lanes compute (converged shuffles); lanes 0..1 store.
    int   qi = lane & (QPW - 1);
    int   q  = qbase + qi;
    float myqsq = qsq[qi];

    float lg[NL];
    float mn =  3.4e38f, mx = -3.4e38f;
#pragma unroll
    for (int n = 0; n < NWAY; n++) {
        float sn = __shfl_sync(0xffffffffu, ssq_r, n);
        float v  = 2.0f * dot[qi][n] - sn - myqsq;
        lg[n] = v;
        mn = fminf(mn, v);
        mx = fmaxf(mx, v);
    }
    lg[NWAY] = mn - 1.0f;

    float ex[NL];
    float se = 0.0f;
#pragma unroll
    for (int i = 0; i < NL; i++) {
        ex[i] = __expf(lg[i] - mx);
        se += ex[i];
    }
    float inv = 1.0f / se;

    int   amax = 0;
    float bv   = lg[0];
#pragma unroll
    for (int i = 1; i < NL; i++)
        if (lg[i] > bv) { bv = lg[i]; amax = i; }

    if (lane < QPW) {
        // Output layout: fh[NQ*NL] | ph[NQ*NL] | yh_top[NQ] | ph_top[NQ]
        float* fh = out + (size_t)q * NL;
#pragma unroll
        for (int i = 0; i < NL; i++) fh[i] = lg[i];

        if (out_size >= 2 * NQ * NL) {
            float* ph = out + (size_t)NQ * NL + (size_t)q * NL;
#pragma unroll
            for (int i = 0; i < NL; i++) ph[i] = ex[i] * inv;
        }
        if (out_size >= 2 * NQ * NL + NQ)
            out[2 * NQ * NL + q] = (float)amax;
        if (out_size >= 2 * NQ * NL + 2 * NQ)
            out[2 * NQ * NL + NQ + q] = ex[amax] * inv;
    }
}

extern "C" void kernel_launch(void* const* d_in, const int* in_sizes, int n_in,
                              void* d_out, int out_size) {
    const float* support = (const float*)d_in[0];
    const float* query   = (const float*)d_in[1];
    float* out = (float*)d_out;

    proto_kernel<<<BB * NWAY, 128>>>(support);
    main_kernel<<<NBLK, 128>>>(query, out, out_size);
}

// round 4
// speedup vs baseline: 1.1693x; 1.0156x over previous
#include <cuda_runtime.h>

#define BB     8
#define NWAY   10
#define KSHOT  5
#define QN     500
#define DD     768
#define NQ     (BB * QN)        // 4000
#define NL     (NWAY + 1)       // 11
#define QPW    2                // queries per warp
#define WTOT   (NQ / QPW)       // 2000 warps
#define WPE    (QN / QPW)       // 250 warps per episode (exact)
#define BLKW   4                // warps per block
#define NBLK   (WTOT / BLKW)    // 500 blocks

__device__ float g_S[BB * NWAY * DD];
__device__ float g_ssq[BB * NWAY];

// ---------------------------------------------------------------------------
// Kernel 1: prototypes + squared norms. One block per (b,n).
// ---------------------------------------------------------------------------
__global__ void __launch_bounds__(128) proto_kernel(const float* __restrict__ sup) {
    int bn = blockIdx.x;            // 0..79
    int t  = threadIdx.x;           // 0..127
    const float* base = sup + (size_t)bn * KSHOT * DD;
    float part = 0.0f;
#pragma unroll
    for (int j = 0; j < DD / 128; j++) {
        int d = t + j * 128;
        float s = 0.0f;
#pragma unroll
        for (int k = 0; k < KSHOT; k++) s += base[k * DD + d];
        s *= 0.2f;
        g_S[bn * DD + d] = s;
        part += s * s;
    }
#pragma unroll
    for (int off = 16; off; off >>= 1)
        part += __shfl_xor_sync(0xffffffffu, part, off);
    __shared__ float red[4];
    if ((t & 31) == 0) red[t >> 5] = part;
    __syncthreads();
    if (t == 0) g_ssq[bn] = red[0] + red[1] + red[2] + red[3];
}

// ---------------------------------------------------------------------------
// Kernel 2: one warp per 2 queries. ALL query loads hoisted into one burst
// (MLP=12) so each warp pays exactly one DRAM round-trip; S loads are L1-hit.
// logits[n] = 2 s.q - ||s||^2 - ||q||^2
// ---------------------------------------------------------------------------
__global__ void __launch_bounds__(128, 4) main_kernel(const float* __restrict__ qin,
                                                      float* __restrict__ out,
                                                      int out_size) {
    int wid  = blockIdx.x * BLKW + (threadIdx.x >> 5);   // 0..1999
    int lane = threadIdx.x & 31;

    int b     = wid / WPE;
    int qbase = b * QN + (wid % WPE) * QPW;

    float ssq_r = (lane < NWAY) ? g_ssq[b * NWAY + lane] : 0.0f;

    const float4* __restrict__ qv = (const float4*)(qin + (size_t)qbase * DD);
    const float4* __restrict__ sv = (const float4*)(g_S + (size_t)b * NWAY * DD);

    // ---- hoisted query load burst: 12 independent LDG.128 in flight ----
    float4 q[QPW][6];
#pragma unroll
    for (int qi = 0; qi < QPW; qi++)
#pragma unroll
        for (int j = 0; j < 6; j++)
            q[qi][j] = qv[qi * (DD / 4) + lane + 32 * j];

    float dot[QPW][NWAY];
    float qsq[QPW];
#pragma unroll
    for (int qi = 0; qi < QPW; qi++) {
        qsq[qi] = 0.0f;
#pragma unroll
        for (int n = 0; n < NWAY; n++) dot[qi][n] = 0.0f;
    }

#pragma unroll
    for (int qi = 0; qi < QPW; qi++)
#pragma unroll
        for (int j = 0; j < 6; j++)
            qsq[qi] += q[qi][j].x * q[qi][j].x + q[qi][j].y * q[qi][j].y
                     + q[qi][j].z * q[qi][j].z + q[qi][j].w * q[qi][j].w;

#pragma unroll
    for (int j = 0; j < 6; j++) {
#pragma unroll
        for (int n = 0; n < NWAY; n++) {
            float4 s = sv[n * (DD / 4) + lane + 32 * j];
#pragma unroll
            for (int qi = 0; qi < QPW; qi++) {
                dot[qi][n] += s.x * q[qi][j].x + s.y * q[qi][j].y
                            + s.z * q[qi][j].z + s.w * q[qi][j].w;
            }
        }
    }

    // Butterfly-reduce 22 accumulators across the warp
#pragma unroll
    for (int qi = 0; qi < QPW; qi++) {
#pragma unroll
        for (int n = 0; n < NWAY; n++) {
#pragma unroll
            for (int off = 16; off; off >>= 1)
                dot[qi][n] += __shfl_xor_sync(0xffffffffu, dot[qi][n], off);
        }
#pragma unroll
        for (int off = 16; off; off >>= 1)
            qsq[qi] += __shfl_xor_sync(0xffffffffu, qsq[qi], off);
    }

    // Epilogue: all lanes compute (converged shuffles); lanes 0..1 store.
    int   qi = lane & (QPW - 1);
    int   qq = qbase + qi;
    float myqsq = qsq[qi];

    float lg[NL];
    float mn =  3.4e38f, mx = -3.4e38f;
#pragma unroll
    for (int n = 0; n < NWAY; n++) {
        float sn = __shfl_sync(0xffffffffu, ssq_r, n);
        float v  = 2.0f * dot[qi][n] - sn - myqsq;
        lg[n] = v;
        mn = fminf(mn, v);
        mx = fmaxf(mx, v);
    }
    lg[NWAY] = mn - 1.0f;

    float ex[NL];
    float se = 0.0f;
#pragma unroll
    for (int i = 0; i < NL; i++) {
        ex[i] = __expf(lg[i] - mx);
        se += ex[i];
    }
    float inv = 1.0f / se;

    int   amax = 0;
    float bv   = lg[0];
#pragma unroll
    for (int i = 1; i < NL; i++)
        if (lg[i] > bv) { bv = lg[i]; amax = i; }

    if (lane < QPW) {
        // Output layout: fh[NQ*NL] | ph[NQ*NL] | yh_top[NQ] | ph_top[NQ]
        float* fh = out + (size_t)qq * NL;
#pragma unroll
        for (int i = 0; i < NL; i++) fh[i] = lg[i];

        if (out_size >= 2 * NQ * NL) {
            float* ph = out + (size_t)NQ * NL + (size_t)qq * NL;
#pragma unroll
            for (int i = 0; i < NL; i++) ph[i] = ex[i] * inv;
        }
        if (out_size >= 2 * NQ * NL + NQ)
            out[2 * NQ * NL + qq] = (float)amax;
        if (out_size >= 2 * NQ * NL + 2 * NQ)
            out[2 * NQ * NL + NQ + qq] = ex[amax] * inv;
    }
}

extern "C" void kernel_launch(void* const* d_in, const int* in_sizes, int n_in,
                              void* d_out, int out_size) {
    const float* support = (const float*)d_in[0];
    const float* query   = (const float*)d_in[1];
    float* out = (float*)d_out;

    proto_kernel<<<BB * NWAY, 128>>>(support);
    main_kernel<<<NBLK, 128>>>(query, out, out_size);
}